// round 10
// baseline (speedup 1.0000x reference)
#include <cuda_runtime.h>
#include <cuda_fp16.h>

// DeformationGrid: trilinear interpolation of a (160,160,160,3) f32 grid at
// 4,194,304 random points.
//
// R8: trilerp was latency-bound (no pipe >61%, 1.85x above its 2.25-
// wavefront/point floor). Each lane-pair now processes TWO points, issuing
// all four 16B gathers up front -> 2x outstanding loads per warp.
// Repack: TY 20->10 halves SMEM per CTA -> ~2x CTAs/SM.

static constexpr int NX = 160, NY = 160, NZ = 160;
static constexpr int NVOX = NX * NY * NZ;

// 16B fp16 z-pair entry, y-fastest: g_grid[(x*NZ + z)*NY + y]. 65.5 MB.
__device__ uint4 g_grid[NVOX];

__device__ __forceinline__ unsigned pack2(float a, float b) {
    __half2 h = __floats2half2_rn(a, b);
    return *reinterpret_cast<unsigned*>(&h);
}
__device__ __forceinline__ float2 unpk2(unsigned u) {
    __half2 h = *reinterpret_cast<__half2*>(&u);
    return __half22float2(h);
}

// ---------------------------------------------------------------------------
// Repack: theta (x,y,z,c) f32 -> g_grid[(x*NZ+z)*NY+y] fp16 z-pair entries.
// Per-block slab = (1 x, TY y, full z): contiguous source -> float4 streaming.
// ---------------------------------------------------------------------------
static constexpr int TY = 10;                // y-rows per block
static constexpr int ROWF = NZ * 3;          // 480 floats per y-row
static constexpr int SROW = ROWF + 3;        // 483: mod 32 = 3 -> conflict-free

__global__ void __launch_bounds__(256)
repack_kernel(const float* __restrict__ theta) {
    __shared__ float s[TY * SROW];           // 19,320 B -> ~11 CTAs/SM

    int b = blockIdx.x;
    int tyi = b % (NY / TY);                 // 16 y-tiles
    int x   = b / (NY / TY);
    int y0 = tyi * TY;

    // Contiguous TY*480-float source block, float4 streaming loads.
    const float4* src = reinterpret_cast<const float4*>(
        theta + (size_t)(x * NY + y0) * ROWF);
    for (int t = threadIdx.x; t < TY * ROWF / 4; t += 256) {
        float4 v = __ldcs(src + t);
        int off = t * 4;                     // never crosses a 480-float row
        int row = off / ROWF;
        int col = off - row * ROWF;
        float* d = s + row * SROW + col;
        d[0] = v.x; d[1] = v.y; d[2] = v.z; d[3] = v.w;
    }
    __syncthreads();

    // y-fastest entry writes, coalesced 16B stores.
    for (int e = threadIdx.x; e < NZ * TY; e += 256) {
        int y = e % TY;
        int z = e / TY;
        const float* r = s + y * SROW + z * 3;
        float a0 = r[0], a1 = r[1], a2 = r[2];
        bool in = (z + 1 < NZ);              // z-edge partner weight is 0
        float b0 = in ? r[3] : 0.0f;
        float b1 = in ? r[4] : 0.0f;
        float b2 = in ? r[5] : 0.0f;
        uint4 E;
        E.x = pack2(a0, a1);
        E.y = pack2(a2, 0.0f);
        E.z = pack2(b0, b1);
        E.w = pack2(b2, 0.0f);
        g_grid[(x * NZ + z) * NY + (y0 + y)] = E;
    }
}

// ---------------------------------------------------------------------------
// Trilerp: lane-pair per point, 2 points per thread for MLP.
// Lane 2j handles y-row iy, lane 2j+1 handles iy+1; their addresses in each
// gather instruction are 16B apart -> merged L1 wavefront.
// ---------------------------------------------------------------------------
struct PointSetup {
    int e0, e1;          // grid entry indices (x0, x1)
    float wx0, wx1, wyr, wz0, wz1;
};

__device__ __forceinline__ PointSetup setup_point(
    const float* __restrict__ coords, int p, int r) {
    float cx = __ldcs(coords + 3 * p + 0);
    float cy = __ldcs(coords + 3 * p + 1);
    float cz = __ldcs(coords + 3 * p + 2);

    float px = cx * (float)(NX - 1);
    float py = cy * (float)(NY - 1);
    float pz = cz * (float)(NZ - 1);
    float fx = floorf(px), fy = floorf(py), fz = floorf(pz);
    float tx = px - fx, ty = py - fy, tz = pz - fz;
    int ix = (int)fx, iy = (int)fy, iz = (int)fz;

    // Per-axis validity folded into axis weights (reference: cval=0 outside).
    bool vx0 = (ix >= 0) && (ix < NX);
    bool vx1 = (ix + 1 >= 0) && (ix + 1 < NX);
    bool vy0 = (iy >= 0) && (iy < NY);
    bool vy1 = (iy + 1 >= 0) && (iy + 1 < NY);
    bool vz0 = (iz >= 0) && (iz < NZ);
    bool vz1 = (iz + 1 >= 0) && (iz + 1 < NZ);

    PointSetup st;
    st.wx0 = vx0 ? (1.0f - tx) : 0.0f;
    st.wx1 = vx1 ? tx : 0.0f;
    float wy0 = vy0 ? (1.0f - ty) : 0.0f;
    float wy1 = vy1 ? ty : 0.0f;
    st.wz0 = vz0 ? (1.0f - tz) : 0.0f;
    st.wz1 = vz1 ? tz : 0.0f;
    st.wyr = r ? wy1 : wy0;

    int ix0 = min(max(ix, 0), NX - 1);
    int ix1 = min(max(ix + 1, 0), NX - 1);
    int iy0 = min(max(iy, 0), NY - 1);
    int iz0 = min(max(iz, 0), NZ - 1);
    int yr = min(iy0 + r, NY - 1);

    st.e0 = (ix0 * NZ + iz0) * NY + yr;
    st.e1 = (ix1 * NZ + iz0) * NY + yr;
    return st;
}

__device__ __forceinline__ void blend_point(
    const PointSetup& st, uint4 A, uint4 B,
    float& sx, float& sy, float& sz) {
    float2 Az0 = unpk2(A.x);  float Az0z = unpk2(A.y).x;
    float2 Az1 = unpk2(A.z);  float Az1z = unpk2(A.w).x;
    float2 Bz0 = unpk2(B.x);  float Bz0z = unpk2(B.y).x;
    float2 Bz1 = unpk2(B.z);  float Bz1z = unpk2(B.w).x;

    sx = st.wyr * (st.wx0 * fmaf(st.wz0, Az0.x, st.wz1 * Az1.x) +
                   st.wx1 * fmaf(st.wz0, Bz0.x, st.wz1 * Bz1.x));
    sy = st.wyr * (st.wx0 * fmaf(st.wz0, Az0.y, st.wz1 * Az1.y) +
                   st.wx1 * fmaf(st.wz0, Bz0.y, st.wz1 * Bz1.y));
    sz = st.wyr * (st.wx0 * fmaf(st.wz0, Az0z, st.wz1 * Az1z) +
                   st.wx1 * fmaf(st.wz0, Bz0z, st.wz1 * Bz1z));
}

__global__ void __launch_bounds__(256)
trilerp_kernel(const float* __restrict__ coords,
               float* __restrict__ out,
               int n) {
    int gid = blockIdx.x * blockDim.x + threadIdx.x;
    int r = gid & 1;                 // y-role within the lane pair
    int p0 = (gid >> 1) * 2;         // this pair's first point
    if (p0 >= n) return;
    int p1 = p0 + 1;
    bool has1 = (p1 < n);

    // Set up both points, then issue ALL gathers before consuming any
    // (4 outstanding LDG.E.128 per lane -> latency hiding).
    PointSetup s0 = setup_point(coords, p0, r);
    PointSetup s1 = setup_point(coords, has1 ? p1 : p0, r);

    uint4 A0 = __ldg(&g_grid[s0.e0]);
    uint4 B0 = __ldg(&g_grid[s0.e1]);
    uint4 A1 = __ldg(&g_grid[s1.e0]);
    uint4 B1 = __ldg(&g_grid[s1.e1]);

    float x0, y0, z0, x1, y1, z1;
    blend_point(s0, A0, B0, x0, y0, z0);
    blend_point(s1, A1, B1, x1, y1, z1);

    // Combine the two y rows across the lane pair.
    x0 += __shfl_xor_sync(0xFFFFFFFFu, x0, 1);
    y0 += __shfl_xor_sync(0xFFFFFFFFu, y0, 1);
    z0 += __shfl_xor_sync(0xFFFFFFFFu, z0, 1);
    x1 += __shfl_xor_sync(0xFFFFFFFFu, x1, 1);
    y1 += __shfl_xor_sync(0xFFFFFFFFu, y1, 1);
    z1 += __shfl_xor_sync(0xFFFFFFFFu, z1, 1);

    if (r == 0) {
        __stcs(out + 3 * p0 + 0, x0);
        __stcs(out + 3 * p0 + 1, y0);
        __stcs(out + 3 * p0 + 2, z0);
        if (has1) {
            __stcs(out + 3 * p1 + 0, x1);
            __stcs(out + 3 * p1 + 1, y1);
            __stcs(out + 3 * p1 + 2, z1);
        }
    }
}

extern "C" void kernel_launch(void* const* d_in, const int* in_sizes, int n_in,
                              void* d_out, int out_size) {
    const float* coords = (const float*)d_in[0];   // (N_POINTS, 3) f32
    const float* theta  = (const float*)d_in[1];   // (160,160,160,3) f32
    float* out = (float*)d_out;                    // (N_POINTS, 3) f32

    int n = in_sizes[0] / 3;

    int repack_blocks = NX * (NY / TY);            // 160 * 16 = 2560
    repack_kernel<<<repack_blocks, 256>>>(theta);

    // One thread per point (each lane-pair covers 2 points).
    int blocks = (n + 255) / 256;
    trilerp_kernel<<<blocks, 256>>>(coords, out, n);
}